// round 14
// baseline (speedup 1.0000x reference)
#include <cuda_runtime.h>
#include <cuda_bf16.h>
#include <cstdint>
#include <math.h>

#define N_NODES 50000
#define N_EDGES 800000
#define D 128

// ---------------- static scratch ----------------
__device__ __align__(16) __nv_bfloat16 g_hiA[N_NODES * D];
__device__ __align__(16) __nv_bfloat16 g_loA[N_NODES * D];
__device__ __align__(16) __nv_bfloat16 g_hiB[N_NODES * D];
__device__ __align__(16) __nv_bfloat16 g_loB[N_NODES * D];
__device__ float g_hn[N_NODES * D];
__device__ int   g_deg[N_NODES];
__device__ float g_invdeg[N_NODES];
__device__ int   g_rowptr[N_NODES + 1];
__device__ int   g_pos[N_NODES];
__device__ int   g_col[N_EDGES];
__device__ __align__(16) __nv_bfloat16 g_Whi[8 * 16384];
__device__ __align__(16) __nv_bfloat16 g_Wlo[8 * 16384];

// ---------------- helpers ----------------
__device__ __forceinline__ uint32_t smem_u32(const void* p) {
    uint32_t a;
    asm("{ .reg .u64 t; cvta.to.shared.u64 t, %1; cvt.u32.u64 %0, t; }" : "=r"(a) : "l"(p));
    return a;
}
__device__ __forceinline__ void ldsm_x4(uint32_t* r, uint32_t addr) {
    asm volatile("ldmatrix.sync.aligned.m8n8.x4.shared.b16 {%0,%1,%2,%3}, [%4];"
                 : "=r"(r[0]), "=r"(r[1]), "=r"(r[2]), "=r"(r[3]) : "r"(addr));
}
__device__ __forceinline__ void ldsm_x2t(uint32_t* r, uint32_t addr) {
    asm volatile("ldmatrix.sync.aligned.m8n8.x2.trans.shared.b16 {%0,%1}, [%2];"
                 : "=r"(r[0]), "=r"(r[1]) : "r"(addr));
}
__device__ __forceinline__ void mma_bf16(float* c, const uint32_t* a, const uint32_t* b) {
    asm volatile(
        "mma.sync.aligned.m16n8k16.row.col.f32.bf16.bf16.f32 "
        "{%0,%1,%2,%3}, {%4,%5,%6,%7}, {%8,%9}, {%0,%1,%2,%3};"
        : "+f"(c[0]), "+f"(c[1]), "+f"(c[2]), "+f"(c[3])
        : "r"(a[0]), "r"(a[1]), "r"(a[2]), "r"(a[3]), "r"(b[0]), "r"(b[1]));
}
__device__ __forceinline__ void split_pack4(float4 v, uint2& hi, uint2& lo) {
    __nv_bfloat16 h0 = __float2bfloat16(v.x);
    __nv_bfloat16 h1 = __float2bfloat16(v.y);
    __nv_bfloat16 h2 = __float2bfloat16(v.z);
    __nv_bfloat16 h3 = __float2bfloat16(v.w);
    __nv_bfloat16 l0 = __float2bfloat16(v.x - __bfloat162float(h0));
    __nv_bfloat16 l1 = __float2bfloat16(v.y - __bfloat162float(h1));
    __nv_bfloat16 l2 = __float2bfloat16(v.z - __bfloat162float(h2));
    __nv_bfloat16 l3 = __float2bfloat16(v.w - __bfloat162float(h3));
    hi.x = (uint32_t)__bfloat16_as_ushort(h0) | ((uint32_t)__bfloat16_as_ushort(h1) << 16);
    hi.y = (uint32_t)__bfloat16_as_ushort(h2) | ((uint32_t)__bfloat16_as_ushort(h3) << 16);
    lo.x = (uint32_t)__bfloat16_as_ushort(l0) | ((uint32_t)__bfloat16_as_ushort(l1) << 16);
    lo.y = (uint32_t)__bfloat16_as_ushort(l2) | ((uint32_t)__bfloat16_as_ushort(l3) << 16);
}
__device__ __forceinline__ uint32_t split_pack2(float x0, float x1, uint32_t& lo) {
    __nv_bfloat16 h0 = __float2bfloat16(x0);
    __nv_bfloat16 h1 = __float2bfloat16(x1);
    __nv_bfloat16 l0 = __float2bfloat16(x0 - __bfloat162float(h0));
    __nv_bfloat16 l1 = __float2bfloat16(x1 - __bfloat162float(h1));
    lo = (uint32_t)__bfloat16_as_ushort(l0) | ((uint32_t)__bfloat16_as_ushort(l1) << 16);
    return (uint32_t)__bfloat16_as_ushort(h0) | ((uint32_t)__bfloat16_as_ushort(h1) << 16);
}
// 16B async copy; src_sz = 16 (copy) or 0 (zero-fill)
__device__ __forceinline__ void cp_async16(uint32_t saddr, const void* gptr, uint32_t src_sz) {
    asm volatile("cp.async.cg.shared.global [%0], [%1], 16, %2;"
                 :: "r"(saddr), "l"(gptr), "r"(src_sz));
}
#define CP_COMMIT() asm volatile("cp.async.commit_group;" ::: "memory")
#define CP_WAIT0()  asm volatile("cp.async.wait_group 0;" ::: "memory")

// ---------------- CSR build ----------------
__global__ void count_kernel(const int* __restrict__ dst) {
    int e = blockIdx.x * blockDim.x + threadIdx.x;
    if (e < N_EDGES) atomicAdd(&g_deg[dst[e]], 1);
}
__global__ void scan_kernel() {
    __shared__ int part[1024];
    const int CH = (N_NODES + 1023) / 1024;
    int t = threadIdx.x;
    int start = t * CH;
    int end = start + CH; if (end > N_NODES) end = N_NODES;
    int s = 0;
    for (int i = start; i < end; i++) s += g_deg[i];
    part[t] = s;
    __syncthreads();
    for (int off = 1; off < 1024; off <<= 1) {
        int v = 0;
        if (t >= off) v = part[t - off];
        __syncthreads();
        if (t >= off) part[t] += v;
        __syncthreads();
    }
    int run = (t == 0) ? 0 : part[t - 1];
    for (int i = start; i < end; i++) {
        g_rowptr[i] = run;
        g_pos[i]    = run;
        int d = g_deg[i];
        g_invdeg[i] = 1.0f / (float)(d > 1 ? d : 1);
        run += d;
    }
    if (t == 1023) g_rowptr[N_NODES] = part[1023];
}
__global__ void fill_kernel(const int* __restrict__ src, const int* __restrict__ dst) {
    int e = blockIdx.x * blockDim.x + threadIdx.x;
    if (e < N_EDGES) {
        int d = dst[e];
        int idx = atomicAdd(&g_pos[d], 1);
        g_col[idx] = src[e];
    }
}

// ---------------- prep: zero degrees + W fp32 -> hi/lo bf16 ----------------
__global__ void prep_kernel(const float* __restrict__ W1, const float* __restrict__ W2,
                            const float* __restrict__ Wself, const float* __restrict__ Wneigh) {
    int idx = blockIdx.x * blockDim.x + threadIdx.x;
    if (idx < N_NODES) g_deg[idx] = 0;
    if (idx >= 8 * 16384) return;
    int slot = idx >> 14, off = idx & 16383;
    const float* src;
    if (slot == 0)      src = W1;
    else if (slot == 1) src = W2;
    else if (slot < 5)  src = Wself + (size_t)(slot - 2) * 16384;
    else                src = Wneigh + (size_t)(slot - 5) * 16384;
    float v = src[off];
    __nv_bfloat16 h = __float2bfloat16(v);
    g_Whi[idx] = h;
    g_Wlo[idx] = __float2bfloat16(v - __bfloat162float(h));
}

// ---------------- mean aggregation over full-precision bf16 pair ----------------
__global__ void agg_pair_kernel(const __nv_bfloat16* __restrict__ hhi,
                                const __nv_bfloat16* __restrict__ hlo,
                                float* __restrict__ hn) {
    int wid  = (blockIdx.x * blockDim.x + threadIdx.x) >> 5;
    int lane = threadIdx.x & 31;
    if (wid >= N_NODES) return;
    int beg = g_rowptr[wid], end = g_rowptr[wid + 1];
    float4 acc = make_float4(0.f, 0.f, 0.f, 0.f);
    for (int e = beg; e < end; e++) {
        size_t rb = (size_t)g_col[e] * D + lane * 4;
        uint2 uh = *(const uint2*)(hhi + rb);
        uint2 ul = *(const uint2*)(hlo + rb);
        float2 ha = __bfloat1622float2(*(__nv_bfloat162*)&uh.x);
        float2 hb = __bfloat1622float2(*(__nv_bfloat162*)&uh.y);
        float2 la = __bfloat1622float2(*(__nv_bfloat162*)&ul.x);
        float2 lb = __bfloat1622float2(*(__nv_bfloat162*)&ul.y);
        acc.x += ha.x + la.x;
        acc.y += ha.y + la.y;
        acc.z += hb.x + lb.x;
        acc.w += hb.y + lb.y;
    }
    float inv = g_invdeg[wid];
    acc.x *= inv; acc.y *= inv; acc.z *= inv; acc.w *= inv;
    *(float4*)(hn + (size_t)wid * D + lane * 4) = acc;
}

// ---------------- GEMM tile config (M tile = 64, 2 blocks/SM) ----------------
#define PITCH 272
#define MTILE 64
#define A_TILE_BYTES (MTILE * PITCH)   // 17408
#define B_TILE_BYTES (128 * PITCH)     // 34816
#define SMEM_TOTAL_BYTES (2 * A_TILE_BYTES + 2 * B_TILE_BYTES)  // 104448
#define STG_PITCH 132

__device__ __forceinline__ void load_split_A(const float* __restrict__ src, int row0, int n,
                                             char* As_hi, char* As_lo, int tid) {
    #pragma unroll 4
    for (int i = tid; i < 2048; i += 256) {
        int r = i >> 5, c = (i & 31) << 2;
        int gr = row0 + r;
        float4 v = make_float4(0.f, 0.f, 0.f, 0.f);
        if (gr < n) v = *(const float4*)(src + (size_t)gr * D + c);
        uint2 h, l;
        split_pack4(v, h, l);
        *(uint2*)(As_hi + r * PITCH + c * 2) = h;
        *(uint2*)(As_lo + r * PITCH + c * 2) = l;
    }
}

// async A-load from bf16 pair arrays (pure copy)
__device__ __forceinline__ void load_A_pair_async(const __nv_bfloat16* __restrict__ hi,
                                                  const __nv_bfloat16* __restrict__ lo,
                                                  int row0, int n, uint32_t as_hi_base, int tid) {
    #pragma unroll 4
    for (int i = tid; i < 2048; i += 256) {
        int arr = i >> 10;
        int j = i & 1023;
        int r = j >> 4, c = (j & 15) << 3;
        int gr = row0 + r;
        uint32_t sz = (gr < n) ? 16u : 0u;
        int grc = (gr < n) ? gr : 0;
        const __nv_bfloat16* src = arr ? lo : hi;
        cp_async16(as_hi_base + arr * A_TILE_BYTES + r * PITCH + c * 2,
                   src + (size_t)grc * D + c, sz);
    }
}

__device__ __forceinline__ void stage_split_A(const float* __restrict__ stg,
                                              char* As_hi, char* As_lo, int tid) {
    #pragma unroll 4
    for (int i = tid; i < 2048; i += 256) {
        int r = i >> 5, c = (i & 31) << 2;
        float4 v = *(const float4*)(stg + r * STG_PITCH + c);
        uint2 h, l;
        split_pack4(v, h, l);
        *(uint2*)(As_hi + r * PITCH + c * 2) = h;
        *(uint2*)(As_lo + r * PITCH + c * 2) = l;
    }
}

// async W-copy into Bs hi/lo
__device__ __forceinline__ void load_B_async(int slot, uint32_t bs_hi_base, int tid) {
    const __nv_bfloat16* whi = g_Whi + (size_t)slot * 16384;
    const __nv_bfloat16* wlo = g_Wlo + (size_t)slot * 16384;
    #pragma unroll 4
    for (int i = tid; i < 2048; i += 256) {
        int r = i >> 4, c = (i & 15) << 3;
        cp_async16(bs_hi_base + r * PITCH + c * 2, whi + r * D + c, 16u);
        cp_async16(bs_hi_base + B_TILE_BYTES + r * PITCH + c * 2, wlo + r * D + c, 16u);
    }
}

__device__ __forceinline__ void mma_mainloop(float acc[2][4][4], uint32_t a_hi0, uint32_t b_hi0) {
    #pragma unroll
    for (int k = 0; k < 8; k++) {
        uint32_t ah[2][4], al[2][4], bh[4][2], bl[4][2];
        #pragma unroll
        for (int nt = 0; nt < 4; nt++) {
            ldsm_x2t(bh[nt], b_hi0 + (uint32_t)k * (16 * PITCH) + nt * 16);
            ldsm_x2t(bl[nt], b_hi0 + B_TILE_BYTES + (uint32_t)k * (16 * PITCH) + nt * 16);
        }
        #pragma unroll
        for (int mt = 0; mt < 2; mt++) {
            ldsm_x4(ah[mt], a_hi0 + (uint32_t)mt * (16 * PITCH) + k * 32);
            ldsm_x4(al[mt], a_hi0 + A_TILE_BYTES + (uint32_t)mt * (16 * PITCH) + k * 32);
        }
        #pragma unroll
        for (int mt = 0; mt < 2; mt++)
            #pragma unroll
            for (int nt = 0; nt < 4; nt++) {
                mma_bf16(acc[mt][nt], ah[mt], bh[nt]);
                mma_bf16(acc[mt][nt], ah[mt], bl[nt]);
                mma_bf16(acc[mt][nt], al[mt], bh[nt]);
            }
    }
}

__device__ __forceinline__ void zero_acc(float acc[2][4][4]) {
    #pragma unroll
    for (int mt = 0; mt < 2; mt++)
        #pragma unroll
        for (int nt = 0; nt < 4; nt++)
            #pragma unroll
            for (int q = 0; q < 4; q++) acc[mt][nt][q] = 0.f;
}

template <int ACT, int OUTMODE>
__device__ __forceinline__ void epilogue(float acc[2][4][4], const float* __restrict__ bias,
                                         __nv_bfloat16* __restrict__ out_hi,
                                         __nv_bfloat16* __restrict__ out_lo,
                                         float* __restrict__ out_f32,
                                         int row0, int n, int wm, int wn, int lane) {
    int mrow = lane >> 2;
    int mcol = (lane & 3) * 2;
    #pragma unroll
    for (int mt = 0; mt < 2; mt++)
        #pragma unroll
        for (int half = 0; half < 2; half++) {
            int gr = row0 + wm + mt * 16 + mrow + half * 8;
            if (gr < n) {
                size_t rb = (size_t)gr * D;
                #pragma unroll
                for (int nt = 0; nt < 4; nt++) {
                    int col = wn + nt * 8 + mcol;
                    float x0 = acc[mt][nt][half * 2 + 0];
                    float x1 = acc[mt][nt][half * 2 + 1];
                    if (bias) { x0 += bias[col]; x1 += bias[col + 1]; }
                    if (ACT == 1)      { x0 = tanhf(x0); x1 = tanhf(x1); }
                    else if (ACT == 2) { x0 = x0 / (1.f + expf(-x0)); x1 = x1 / (1.f + expf(-x1)); }
                    if (OUTMODE == 0) {
                        uint32_t lo, hi = split_pack2(x0, x1, lo);
                        *(uint32_t*)(out_hi + rb + col) = hi;
                        *(uint32_t*)(out_lo + rb + col) = lo;
                    } else {
                        *(float2*)(out_f32 + rb + col) = make_float2(x0, x1);
                    }
                }
            }
        }
}

// ---------------- fused fc_in: pair_out = tanh(h@W1+b1)@W2 + b2 ----------------
__global__ void __launch_bounds__(256, 2)
fc_fused_kernel(const float* __restrict__ A, const float* __restrict__ b1,
                const float* __restrict__ b2,
                __nv_bfloat16* __restrict__ out_hi, __nv_bfloat16* __restrict__ out_lo, int n) {
    extern __shared__ char smem[];
    char* As_hi = smem;
    char* As_lo = smem + A_TILE_BYTES;
    char* Bs_hi = smem + 2 * A_TILE_BYTES;
    float* staging = (float*)(smem + 2 * A_TILE_BYTES);

    int tid = threadIdx.x, lane = tid & 31, wid = tid >> 5;
    int row0 = blockIdx.x * MTILE;
    int wm = (wid & 1) * 32;
    int wn = (wid >> 1) * 32;
    int mrow = lane >> 2;
    int mcol = (lane & 3) * 2;

    uint32_t as_base = smem_u32(As_hi);
    uint32_t bs_base = smem_u32(Bs_hi);
    uint32_t a_hi0 = as_base + (uint32_t)(wm + (lane & 15)) * PITCH + (lane >> 4) * 16;
    uint32_t b_hi0 = bs_base + (uint32_t)(lane & 15) * PITCH + wn * 2;

    float acc[2][4][4];
    zero_acc(acc);

    // phase 1: issue async W copy, overlap with A conversion
    load_B_async(0, bs_base, tid);
    CP_COMMIT();
    load_split_A(A, row0, n, As_hi, As_lo, tid);
    CP_WAIT0();
    __syncthreads();
    mma_mainloop(acc, a_hi0, b_hi0);
    __syncthreads();

    #pragma unroll
    for (int mt = 0; mt < 2; mt++)
        #pragma unroll
        for (int half = 0; half < 2; half++) {
            int r = wm + mt * 16 + mrow + half * 8;
            #pragma unroll
            for (int nt = 0; nt < 4; nt++) {
                int col = wn + nt * 8 + mcol;
                staging[r * STG_PITCH + col]     = tanhf(acc[mt][nt][half * 2 + 0] + b1[col]);
                staging[r * STG_PITCH + col + 1] = tanhf(acc[mt][nt][half * 2 + 1] + b1[col + 1]);
            }
        }
    __syncthreads();

    stage_split_A(staging, As_hi, As_lo, tid);
    __syncthreads();          // staging reads done before Bs overwrite

    load_B_async(1, bs_base, tid);
    CP_COMMIT();
    zero_acc(acc);
    CP_WAIT0();
    __syncthreads();

    mma_mainloop(acc, a_hi0, b_hi0);
    epilogue<0, 0>(acc, b2, out_hi, out_lo, nullptr, row0, n, wm, wn, lane);
}

// ---------------- fused SAGE layer: out = act(in@Ws + bias + hn@Wn) ----------------
template <int ACT, int OUTMODE>
__global__ void __launch_bounds__(256, 2)
layer_kernel(const __nv_bfloat16* __restrict__ in_hi, const __nv_bfloat16* __restrict__ in_lo,
             const float* __restrict__ hn, int slot_self, int slot_neigh,
             const float* __restrict__ bias,
             __nv_bfloat16* __restrict__ out_hi, __nv_bfloat16* __restrict__ out_lo,
             float* __restrict__ out_f32, int n) {
    extern __shared__ char smem[];
    char* As_hi = smem;
    char* As_lo = smem + A_TILE_BYTES;
    char* Bs_hi = smem + 2 * A_TILE_BYTES;

    int tid = threadIdx.x, lane = tid & 31, wid = tid >> 5;
    int row0 = blockIdx.x * MTILE;
    int wm = (wid & 1) * 32;
    int wn = (wid >> 1) * 32;

    uint32_t as_base = smem_u32(As_hi);
    uint32_t bs_base = smem_u32(Bs_hi);
    uint32_t a_hi0 = as_base + (uint32_t)(wm + (lane & 15)) * PITCH + (lane >> 4) * 16;
    uint32_t b_hi0 = bs_base + (uint32_t)(lane & 15) * PITCH + wn * 2;

    float acc[2][4][4];
    zero_acc(acc);

    // phase 1: self term (all pure copies — fully async)
    load_B_async(slot_self, bs_base, tid);
    load_A_pair_async(in_hi, in_lo, row0, n, as_base, tid);
    CP_COMMIT();
    CP_WAIT0();
    __syncthreads();
    mma_mainloop(acc, a_hi0, b_hi0);
    __syncthreads();

    // phase 2: neighbor term (async W copy overlapped with hn conversion)
    load_B_async(slot_neigh, bs_base, tid);
    CP_COMMIT();
    load_split_A(hn, row0, n, As_hi, As_lo, tid);
    CP_WAIT0();
    __syncthreads();
    mma_mainloop(acc, a_hi0, b_hi0);

    epilogue<ACT, OUTMODE>(acc, bias, out_hi, out_lo, out_f32, row0, n, wm, wn, lane);
}

// ---------------- launch ----------------
extern "C" void kernel_launch(void* const* d_in, const int* in_sizes, int n_in,
                              void* d_out, int out_size) {
    const float* h_in    = (const float*)d_in[0];
    const int*   src     = (const int*)  d_in[1];
    const int*   dst     = (const int*)  d_in[2];
    const float* W_in1   = (const float*)d_in[3];
    const float* b_in1   = (const float*)d_in[4];
    const float* W_in2   = (const float*)d_in[5];
    const float* b_in2   = (const float*)d_in[6];
    const float* W_self  = (const float*)d_in[7];
    const float* b_self  = (const float*)d_in[8];
    const float* W_neigh = (const float*)d_in[9];
    float* out = (float*)d_out;

    cudaFuncSetAttribute(fc_fused_kernel,    cudaFuncAttributeMaxDynamicSharedMemorySize, SMEM_TOTAL_BYTES);
    cudaFuncSetAttribute(layer_kernel<2, 0>, cudaFuncAttributeMaxDynamicSharedMemorySize, SMEM_TOTAL_BYTES);
    cudaFuncSetAttribute(layer_kernel<1, 1>, cudaFuncAttributeMaxDynamicSharedMemorySize, SMEM_TOTAL_BYTES);

    __nv_bfloat16 *hiA = nullptr, *loA = nullptr, *hiB = nullptr, *loB = nullptr;
    float* hn = nullptr;
    cudaGetSymbolAddress((void**)&hiA, g_hiA);
    cudaGetSymbolAddress((void**)&loA, g_loA);
    cudaGetSymbolAddress((void**)&hiB, g_hiB);
    cudaGetSymbolAddress((void**)&loB, g_loB);
    cudaGetSymbolAddress((void**)&hn,  g_hn);

    const int GEMM_GRID = (N_NODES + MTILE - 1) / MTILE;  // 782
    const int EB = (N_EDGES + 255) / 256;
    const int AGG_GRID = (N_NODES * 32 + 255) / 256;

    // ---- prep + CSR build ----
    prep_kernel<<<512, 256>>>(W_in1, W_in2, W_self, W_neigh);
    count_kernel<<<EB, 256>>>(dst);
    scan_kernel<<<1, 1024>>>();
    fill_kernel<<<EB, 256>>>(src, dst);

    // ---- fc_in fused ----
    fc_fused_kernel<<<GEMM_GRID, 256, SMEM_TOTAL_BYTES>>>(h_in, b_in1, b_in2, hiA, loA, N_NODES);

    // ---- 3 SAGE layers: full-precision pair gather + fused dual-GEMM ----
    agg_pair_kernel<<<AGG_GRID, 256>>>(hiA, loA, hn);
    layer_kernel<2, 0><<<GEMM_GRID, 256, SMEM_TOTAL_BYTES>>>(hiA, loA, hn, 2, 5, b_self + 0 * D,
                                                             hiB, loB, nullptr, N_NODES);

    agg_pair_kernel<<<AGG_GRID, 256>>>(hiB, loB, hn);
    layer_kernel<2, 0><<<GEMM_GRID, 256, SMEM_TOTAL_BYTES>>>(hiB, loB, hn, 3, 6, b_self + 1 * D,
                                                             hiA, loA, nullptr, N_NODES);

    agg_pair_kernel<<<AGG_GRID, 256>>>(hiA, loA, hn);
    layer_kernel<1, 1><<<GEMM_GRID, 256, SMEM_TOTAL_BYTES>>>(hiA, loA, hn, 4, 7, b_self + 2 * D,
                                                             nullptr, nullptr, out, N_NODES);
}

// round 15
// speedup vs baseline: 1.0490x; 1.0490x over previous
#include <cuda_runtime.h>
#include <cuda_bf16.h>
#include <cstdint>
#include <math.h>

#define N_NODES 50000
#define N_EDGES 800000
#define D 128

// ---------------- static scratch ----------------
// inter-layer features: interleaved hi/lo bf16 pairs, row = 256 bf16 = 512 B
// layout: pair[node*256 + 2*j] = hi_j, pair[node*256 + 2*j + 1] = lo_j
__device__ __align__(16) __nv_bfloat16 g_pairA[N_NODES * 2 * D];
__device__ __align__(16) __nv_bfloat16 g_pairB[N_NODES * 2 * D];
__device__ float g_hn[N_NODES * D];
__device__ int   g_deg[N_NODES];
__device__ float g_invdeg[N_NODES];
__device__ int   g_rowptr[N_NODES + 1];
__device__ int   g_pos[N_NODES];
__device__ int   g_col[N_EDGES];
__device__ __align__(16) __nv_bfloat16 g_Whi[8 * 16384];
__device__ __align__(16) __nv_bfloat16 g_Wlo[8 * 16384];

// ---------------- helpers ----------------
__device__ __forceinline__ uint32_t smem_u32(const void* p) {
    uint32_t a;
    asm("{ .reg .u64 t; cvta.to.shared.u64 t, %1; cvt.u32.u64 %0, t; }" : "=r"(a) : "l"(p));
    return a;
}
__device__ __forceinline__ void ldsm_x4(uint32_t* r, uint32_t addr) {
    asm volatile("ldmatrix.sync.aligned.m8n8.x4.shared.b16 {%0,%1,%2,%3}, [%4];"
                 : "=r"(r[0]), "=r"(r[1]), "=r"(r[2]), "=r"(r[3]) : "r"(addr));
}
__device__ __forceinline__ void ldsm_x2t(uint32_t* r, uint32_t addr) {
    asm volatile("ldmatrix.sync.aligned.m8n8.x2.trans.shared.b16 {%0,%1}, [%2];"
                 : "=r"(r[0]), "=r"(r[1]) : "r"(addr));
}
__device__ __forceinline__ void mma_bf16(float* c, const uint32_t* a, const uint32_t* b) {
    asm volatile(
        "mma.sync.aligned.m16n8k16.row.col.f32.bf16.bf16.f32 "
        "{%0,%1,%2,%3}, {%4,%5,%6,%7}, {%8,%9}, {%0,%1,%2,%3};"
        : "+f"(c[0]), "+f"(c[1]), "+f"(c[2]), "+f"(c[3])
        : "r"(a[0]), "r"(a[1]), "r"(a[2]), "r"(a[3]), "r"(b[0]), "r"(b[1]));
}
__device__ __forceinline__ uint32_t prmt(uint32_t a, uint32_t b, uint32_t sel) {
    uint32_t r;
    asm("prmt.b32 %0, %1, %2, %3;" : "=r"(r) : "r"(a), "r"(b), "r"(sel));
    return r;
}
__device__ __forceinline__ void split_pack4(float4 v, uint2& hi, uint2& lo) {
    __nv_bfloat16 h0 = __float2bfloat16(v.x);
    __nv_bfloat16 h1 = __float2bfloat16(v.y);
    __nv_bfloat16 h2 = __float2bfloat16(v.z);
    __nv_bfloat16 h3 = __float2bfloat16(v.w);
    __nv_bfloat16 l0 = __float2bfloat16(v.x - __bfloat162float(h0));
    __nv_bfloat16 l1 = __float2bfloat16(v.y - __bfloat162float(h1));
    __nv_bfloat16 l2 = __float2bfloat16(v.z - __bfloat162float(h2));
    __nv_bfloat16 l3 = __float2bfloat16(v.w - __bfloat162float(h3));
    hi.x = (uint32_t)__bfloat16_as_ushort(h0) | ((uint32_t)__bfloat16_as_ushort(h1) << 16);
    hi.y = (uint32_t)__bfloat16_as_ushort(h2) | ((uint32_t)__bfloat16_as_ushort(h3) << 16);
    lo.x = (uint32_t)__bfloat16_as_ushort(l0) | ((uint32_t)__bfloat16_as_ushort(l1) << 16);
    lo.y = (uint32_t)__bfloat16_as_ushort(l2) | ((uint32_t)__bfloat16_as_ushort(l3) << 16);
}
// pack (x0,x1) -> two interleaved words [h0|l0], [h1|l1]
__device__ __forceinline__ uint2 pack_inter2(float x0, float x1) {
    __nv_bfloat16 h0 = __float2bfloat16(x0);
    __nv_bfloat16 h1 = __float2bfloat16(x1);
    __nv_bfloat16 l0 = __float2bfloat16(x0 - __bfloat162float(h0));
    __nv_bfloat16 l1 = __float2bfloat16(x1 - __bfloat162float(h1));
    uint2 r;
    r.x = (uint32_t)__bfloat16_as_ushort(h0) | ((uint32_t)__bfloat16_as_ushort(l0) << 16);
    r.y = (uint32_t)__bfloat16_as_ushort(h1) | ((uint32_t)__bfloat16_as_ushort(l1) << 16);
    return r;
}

// ---------------- CSR build ----------------
__global__ void count_kernel(const int* __restrict__ dst) {
    int e = blockIdx.x * blockDim.x + threadIdx.x;
    if (e < N_EDGES) atomicAdd(&g_deg[dst[e]], 1);
}
__global__ void scan_kernel() {
    __shared__ int part[1024];
    const int CH = (N_NODES + 1023) / 1024;
    int t = threadIdx.x;
    int start = t * CH;
    int end = start + CH; if (end > N_NODES) end = N_NODES;
    int s = 0;
    for (int i = start; i < end; i++) s += g_deg[i];
    part[t] = s;
    __syncthreads();
    for (int off = 1; off < 1024; off <<= 1) {
        int v = 0;
        if (t >= off) v = part[t - off];
        __syncthreads();
        if (t >= off) part[t] += v;
        __syncthreads();
    }
    int run = (t == 0) ? 0 : part[t - 1];
    for (int i = start; i < end; i++) {
        g_rowptr[i] = run;
        g_pos[i]    = run;
        int d = g_deg[i];
        g_invdeg[i] = 1.0f / (float)(d > 1 ? d : 1);
        run += d;
    }
    if (t == 1023) g_rowptr[N_NODES] = part[1023];
}
__global__ void fill_kernel(const int* __restrict__ src, const int* __restrict__ dst) {
    int e = blockIdx.x * blockDim.x + threadIdx.x;
    if (e < N_EDGES) {
        int d = dst[e];
        int idx = atomicAdd(&g_pos[d], 1);
        g_col[idx] = src[e];
    }
}

// ---------------- prep: zero degrees + W fp32 -> hi/lo bf16 (8 slots) ----------------
__global__ void prep_kernel(const float* __restrict__ W1, const float* __restrict__ W2,
                            const float* __restrict__ Wself, const float* __restrict__ Wneigh) {
    int idx = blockIdx.x * blockDim.x + threadIdx.x;
    if (idx < N_NODES) g_deg[idx] = 0;
    if (idx >= 8 * 16384) return;
    int slot = idx >> 14, off = idx & 16383;
    const float* src;
    if (slot == 0)      src = W1;
    else if (slot == 1) src = W2;
    else if (slot < 5)  src = Wself + (size_t)(slot - 2) * 16384;
    else                src = Wneigh + (size_t)(slot - 5) * 16384;
    float v = src[off];
    __nv_bfloat16 h = __float2bfloat16(v);
    g_Whi[idx] = h;
    g_Wlo[idx] = __float2bfloat16(v - __bfloat162float(h));
}

// ---------------- mean aggregation over interleaved pair (1 load/edge/lane, full precision) ----------------
__global__ void agg_inter_kernel(const __nv_bfloat16* __restrict__ pair, float* __restrict__ hn) {
    int wid  = (blockIdx.x * blockDim.x + threadIdx.x) >> 5;
    int lane = threadIdx.x & 31;
    if (wid >= N_NODES) return;
    int beg = g_rowptr[wid], end = g_rowptr[wid + 1];
    float4 acc = make_float4(0.f, 0.f, 0.f, 0.f);
    int e = beg;
    for (; e + 4 <= end; e += 4) {
        uint4 u0 = *(const uint4*)(pair + (size_t)g_col[e + 0] * 256 + lane * 8);
        uint4 u1 = *(const uint4*)(pair + (size_t)g_col[e + 1] * 256 + lane * 8);
        uint4 u2 = *(const uint4*)(pair + (size_t)g_col[e + 2] * 256 + lane * 8);
        uint4 u3 = *(const uint4*)(pair + (size_t)g_col[e + 3] * 256 + lane * 8);
        // each uint32 = [hi | lo] for one feature; value = hi + lo
        float2 f;
        f = __bfloat1622float2(*(__nv_bfloat162*)&u0.x); acc.x += f.x + f.y;
        f = __bfloat1622float2(*(__nv_bfloat162*)&u0.y); acc.y += f.x + f.y;
        f = __bfloat1622float2(*(__nv_bfloat162*)&u0.z); acc.z += f.x + f.y;
        f = __bfloat1622float2(*(__nv_bfloat162*)&u0.w); acc.w += f.x + f.y;
        f = __bfloat1622float2(*(__nv_bfloat162*)&u1.x); acc.x += f.x + f.y;
        f = __bfloat1622float2(*(__nv_bfloat162*)&u1.y); acc.y += f.x + f.y;
        f = __bfloat1622float2(*(__nv_bfloat162*)&u1.z); acc.z += f.x + f.y;
        f = __bfloat1622float2(*(__nv_bfloat162*)&u1.w); acc.w += f.x + f.y;
        f = __bfloat1622float2(*(__nv_bfloat162*)&u2.x); acc.x += f.x + f.y;
        f = __bfloat1622float2(*(__nv_bfloat162*)&u2.y); acc.y += f.x + f.y;
        f = __bfloat1622float2(*(__nv_bfloat162*)&u2.z); acc.z += f.x + f.y;
        f = __bfloat1622float2(*(__nv_bfloat162*)&u2.w); acc.w += f.x + f.y;
        f = __bfloat1622float2(*(__nv_bfloat162*)&u3.x); acc.x += f.x + f.y;
        f = __bfloat1622float2(*(__nv_bfloat162*)&u3.y); acc.y += f.x + f.y;
        f = __bfloat1622float2(*(__nv_bfloat162*)&u3.z); acc.z += f.x + f.y;
        f = __bfloat1622float2(*(__nv_bfloat162*)&u3.w); acc.w += f.x + f.y;
    }
    for (; e < end; e++) {
        uint4 u = *(const uint4*)(pair + (size_t)g_col[e] * 256 + lane * 8);
        float2 f;
        f = __bfloat1622float2(*(__nv_bfloat162*)&u.x); acc.x += f.x + f.y;
        f = __bfloat1622float2(*(__nv_bfloat162*)&u.y); acc.y += f.x + f.y;
        f = __bfloat1622float2(*(__nv_bfloat162*)&u.z); acc.z += f.x + f.y;
        f = __bfloat1622float2(*(__nv_bfloat162*)&u.w); acc.w += f.x + f.y;
    }
    float inv = g_invdeg[wid];
    acc.x *= inv; acc.y *= inv; acc.z *= inv; acc.w *= inv;
    *(float4*)(hn + (size_t)wid * D + lane * 4) = acc;
}

// ---------------- GEMM tile config (M tile = 64, 2 blocks/SM) ----------------
#define PITCH 272
#define MTILE 64
#define A_TILE_BYTES (MTILE * PITCH)   // 17408
#define B_TILE_BYTES (128 * PITCH)     // 34816
#define SMEM_TOTAL_BYTES (2 * A_TILE_BYTES + 2 * B_TILE_BYTES)  // 104448
#define STG_PITCH 132

__device__ __forceinline__ void load_split_A(const float* __restrict__ src, int row0, int n,
                                             char* As_hi, char* As_lo, int tid) {
    #pragma unroll 4
    for (int i = tid; i < 2048; i += 256) {
        int r = i >> 5, c = (i & 31) << 2;
        int gr = row0 + r;
        float4 v = make_float4(0.f, 0.f, 0.f, 0.f);
        if (gr < n) v = *(const float4*)(src + (size_t)gr * D + c);
        uint2 h, l;
        split_pack4(v, h, l);
        *(uint2*)(As_hi + r * PITCH + c * 2) = h;
        *(uint2*)(As_lo + r * PITCH + c * 2) = l;
    }
}

// A-load from interleaved pair array: uint4 read + 4 PRMT de-interleave
__device__ __forceinline__ void load_A_inter(const __nv_bfloat16* __restrict__ pair,
                                             int row0, int n,
                                             char* As_hi, char* As_lo, int tid) {
    #pragma unroll 4
    for (int i = tid; i < 2048; i += 256) {
        int r = i >> 5, g = i & 31;              // g: group of 4 features
        int gr = row0 + r;
        uint4 u = make_uint4(0u, 0u, 0u, 0u);
        if (gr < n) u = *(const uint4*)(pair + (size_t)gr * 256 + g * 8);
        // u.x=[h0|l0] u.y=[h1|l1] u.z=[h2|l2] u.w=[h3|l3]
        uint2 h, l;
        h.x = prmt(u.x, u.y, 0x5410);   // [h0,h1]
        h.y = prmt(u.z, u.w, 0x5410);   // [h2,h3]
        l.x = prmt(u.x, u.y, 0x7632);   // [l0,l1]
        l.y = prmt(u.z, u.w, 0x7632);   // [l2,l3]
        *(uint2*)(As_hi + r * PITCH + g * 8) = h;
        *(uint2*)(As_lo + r * PITCH + g * 8) = l;
    }
}

__device__ __forceinline__ void stage_split_A(const float* __restrict__ stg,
                                              char* As_hi, char* As_lo, int tid) {
    #pragma unroll 4
    for (int i = tid; i < 2048; i += 256) {
        int r = i >> 5, c = (i & 31) << 2;
        float4 v = *(const float4*)(stg + r * STG_PITCH + c);
        uint2 h, l;
        split_pack4(v, h, l);
        *(uint2*)(As_hi + r * PITCH + c * 2) = h;
        *(uint2*)(As_lo + r * PITCH + c * 2) = l;
    }
}

__device__ __forceinline__ void load_B_prepped(int slot, char* Bs_hi, char* Bs_lo, int tid) {
    const __nv_bfloat16* whi = g_Whi + (size_t)slot * 16384;
    const __nv_bfloat16* wlo = g_Wlo + (size_t)slot * 16384;
    #pragma unroll 4
    for (int i = tid; i < 2048; i += 256) {
        int r = i >> 4, c = (i & 15) << 3;
        *(uint4*)(Bs_hi + r * PITCH + c * 2) = *(const uint4*)(whi + r * D + c);
        *(uint4*)(Bs_lo + r * PITCH + c * 2) = *(const uint4*)(wlo + r * D + c);
    }
}

__device__ __forceinline__ void mma_mainloop(float acc[2][4][4], uint32_t a_hi0, uint32_t b_hi0) {
    #pragma unroll
    for (int k = 0; k < 8; k++) {
        uint32_t ah[2][4], al[2][4], bh[4][2], bl[4][2];
        #pragma unroll
        for (int nt = 0; nt < 4; nt++) {
            ldsm_x2t(bh[nt], b_hi0 + (uint32_t)k * (16 * PITCH) + nt * 16);
            ldsm_x2t(bl[nt], b_hi0 + B_TILE_BYTES + (uint32_t)k * (16 * PITCH) + nt * 16);
        }
        #pragma unroll
        for (int mt = 0; mt < 2; mt++) {
            ldsm_x4(ah[mt], a_hi0 + (uint32_t)mt * (16 * PITCH) + k * 32);
            ldsm_x4(al[mt], a_hi0 + A_TILE_BYTES + (uint32_t)mt * (16 * PITCH) + k * 32);
        }
        #pragma unroll
        for (int mt = 0; mt < 2; mt++)
            #pragma unroll
            for (int nt = 0; nt < 4; nt++) {
                mma_bf16(acc[mt][nt], ah[mt], bh[nt]);
                mma_bf16(acc[mt][nt], ah[mt], bl[nt]);
                mma_bf16(acc[mt][nt], al[mt], bh[nt]);
            }
    }
}

__device__ __forceinline__ void zero_acc(float acc[2][4][4]) {
    #pragma unroll
    for (int mt = 0; mt < 2; mt++)
        #pragma unroll
        for (int nt = 0; nt < 4; nt++)
            #pragma unroll
            for (int q = 0; q < 4; q++) acc[mt][nt][q] = 0.f;
}

// epilogue: OUTMODE 0 -> interleaved pair array; OUTMODE 1 -> fp32
template <int ACT, int OUTMODE>
__device__ __forceinline__ void epilogue(float acc[2][4][4], const float* __restrict__ bias,
                                         __nv_bfloat16* __restrict__ out_pair,
                                         float* __restrict__ out_f32,
                                         int row0, int n, int wm, int wn, int lane) {
    int mrow = lane >> 2;
    int mcol = (lane & 3) * 2;
    #pragma unroll
    for (int mt = 0; mt < 2; mt++)
        #pragma unroll
        for (int half = 0; half < 2; half++) {
            int gr = row0 + wm + mt * 16 + mrow + half * 8;
            if (gr < n) {
                #pragma unroll
                for (int nt = 0; nt < 4; nt++) {
                    int col = wn + nt * 8 + mcol;
                    float x0 = acc[mt][nt][half * 2 + 0];
                    float x1 = acc[mt][nt][half * 2 + 1];
                    if (bias) { x0 += bias[col]; x1 += bias[col + 1]; }
                    if (ACT == 1)      { x0 = tanhf(x0); x1 = tanhf(x1); }
                    else if (ACT == 2) { x0 = x0 / (1.f + expf(-x0)); x1 = x1 / (1.f + expf(-x1)); }
                    if (OUTMODE == 0) {
                        uint2 w = pack_inter2(x0, x1);
                        *(uint2*)(out_pair + (size_t)gr * 256 + col * 2) = w;
                    } else {
                        *(float2*)(out_f32 + (size_t)gr * D + col) = make_float2(x0, x1);
                    }
                }
            }
        }
}

// ---------------- fused fc_in: pair_out = tanh(h@W1+b1)@W2 + b2 ----------------
__global__ void __launch_bounds__(256, 2)
fc_fused_kernel(const float* __restrict__ A, const float* __restrict__ b1,
                const float* __restrict__ b2,
                __nv_bfloat16* __restrict__ out_pair, int n) {
    extern __shared__ char smem[];
    char* As_hi = smem;
    char* As_lo = smem + A_TILE_BYTES;
    char* Bs_hi = smem + 2 * A_TILE_BYTES;
    float* staging = (float*)(smem + 2 * A_TILE_BYTES);

    int tid = threadIdx.x, lane = tid & 31, wid = tid >> 5;
    int row0 = blockIdx.x * MTILE;
    int wm = (wid & 1) * 32;
    int wn = (wid >> 1) * 32;
    int mrow = lane >> 2;
    int mcol = (lane & 3) * 2;

    uint32_t a_hi0 = smem_u32(As_hi) + (uint32_t)(wm + (lane & 15)) * PITCH + (lane >> 4) * 16;
    uint32_t b_hi0 = smem_u32(Bs_hi) + (uint32_t)(lane & 15) * PITCH + wn * 2;

    float acc[2][4][4];
    zero_acc(acc);

    load_split_A(A, row0, n, As_hi, As_lo, tid);
    load_B_prepped(0, Bs_hi, Bs_hi + B_TILE_BYTES, tid);
    __syncthreads();
    mma_mainloop(acc, a_hi0, b_hi0);
    __syncthreads();

    #pragma unroll
    for (int mt = 0; mt < 2; mt++)
        #pragma unroll
        for (int half = 0; half < 2; half++) {
            int r = wm + mt * 16 + mrow + half * 8;
            #pragma unroll
            for (int nt = 0; nt < 4; nt++) {
                int col = wn + nt * 8 + mcol;
                staging[r * STG_PITCH + col]     = tanhf(acc[mt][nt][half * 2 + 0] + b1[col]);
                staging[r * STG_PITCH + col + 1] = tanhf(acc[mt][nt][half * 2 + 1] + b1[col + 1]);
            }
        }
    __syncthreads();

    stage_split_A(staging, As_hi, As_lo, tid);
    __syncthreads();

    load_B_prepped(1, Bs_hi, Bs_hi + B_TILE_BYTES, tid);
    zero_acc(acc);
    __syncthreads();

    mma_mainloop(acc, a_hi0, b_hi0);
    epilogue<0, 0>(acc, b2, out_pair, nullptr, row0, n, wm, wn, lane);
}

// ---------------- fused SAGE layer: out = act(in@Ws + bias + hn@Wn) ----------------
template <int ACT, int OUTMODE>
__global__ void __launch_bounds__(256, 2)
layer_kernel(const __nv_bfloat16* __restrict__ in_pair,
             const float* __restrict__ hn, int slot_self, int slot_neigh,
             const float* __restrict__ bias,
             __nv_bfloat16* __restrict__ out_pair, float* __restrict__ out_f32, int n) {
    extern __shared__ char smem[];
    char* As_hi = smem;
    char* As_lo = smem + A_TILE_BYTES;
    char* Bs_hi = smem + 2 * A_TILE_BYTES;

    int tid = threadIdx.x, lane = tid & 31, wid = tid >> 5;
    int row0 = blockIdx.x * MTILE;
    int wm = (wid & 1) * 32;
    int wn = (wid >> 1) * 32;

    uint32_t a_hi0 = smem_u32(As_hi) + (uint32_t)(wm + (lane & 15)) * PITCH + (lane >> 4) * 16;
    uint32_t b_hi0 = smem_u32(Bs_hi) + (uint32_t)(lane & 15) * PITCH + wn * 2;

    float acc[2][4][4];
    zero_acc(acc);

    // phase 1: self term (A de-interleaved from pair array)
    load_A_inter(in_pair, row0, n, As_hi, As_lo, tid);
    load_B_prepped(slot_self, Bs_hi, Bs_hi + B_TILE_BYTES, tid);
    __syncthreads();
    mma_mainloop(acc, a_hi0, b_hi0);
    __syncthreads();

    // phase 2: neighbor term (A from hn fp32 via split)
    load_split_A(hn, row0, n, As_hi, As_lo, tid);
    load_B_prepped(slot_neigh, Bs_hi, Bs_hi + B_TILE_BYTES, tid);
    __syncthreads();
    mma_mainloop(acc, a_hi0, b_hi0);

    epilogue<ACT, OUTMODE>(acc, bias, out_pair, out_f32, row0, n, wm, wn, lane);
}

// ---------------- launch ----------------
extern "C" void kernel_launch(void* const* d_in, const int* in_sizes, int n_in,
                              void* d_out, int out_size) {
    const float* h_in    = (const float*)d_in[0];
    const int*   src     = (const int*)  d_in[1];
    const int*   dst     = (const int*)  d_in[2];
    const float* W_in1   = (const float*)d_in[3];
    const float* b_in1   = (const float*)d_in[4];
    const float* W_in2   = (const float*)d_in[5];
    const float* b_in2   = (const float*)d_in[6];
    const float* W_self  = (const float*)d_in[7];
    const float* b_self  = (const float*)d_in[8];
    const float* W_neigh = (const float*)d_in[9];
    float* out = (float*)d_out;

    cudaFuncSetAttribute(fc_fused_kernel,    cudaFuncAttributeMaxDynamicSharedMemorySize, SMEM_TOTAL_BYTES);
    cudaFuncSetAttribute(layer_kernel<2, 0>, cudaFuncAttributeMaxDynamicSharedMemorySize, SMEM_TOTAL_BYTES);
    cudaFuncSetAttribute(layer_kernel<1, 1>, cudaFuncAttributeMaxDynamicSharedMemorySize, SMEM_TOTAL_BYTES);

    __nv_bfloat16 *pairA = nullptr, *pairB = nullptr;
    float* hn = nullptr;
    cudaGetSymbolAddress((void**)&pairA, g_pairA);
    cudaGetSymbolAddress((void**)&pairB, g_pairB);
    cudaGetSymbolAddress((void**)&hn,    g_hn);

    const int GEMM_GRID = (N_NODES + MTILE - 1) / MTILE;  // 782
    const int EB = (N_EDGES + 255) / 256;
    const int AGG_GRID = (N_NODES * 32 + 255) / 256;

    // ---- prep + CSR build ----
    prep_kernel<<<512, 256>>>(W_in1, W_in2, W_self, W_neigh);
    count_kernel<<<EB, 256>>>(dst);
    scan_kernel<<<1, 1024>>>();
    fill_kernel<<<EB, 256>>>(src, dst);

    // ---- fc_in fused: pairA = tanh(h@W1+b1)@W2 + b2 ----
    fc_fused_kernel<<<GEMM_GRID, 256, SMEM_TOTAL_BYTES>>>(h_in, b_in1, b_in2, pairA, N_NODES);

    // ---- 3 SAGE layers: interleaved-pair gather (full precision) + fused dual-GEMM ----
    agg_inter_kernel<<<AGG_GRID, 256>>>(pairA, hn);
    layer_kernel<2, 0><<<GEMM_GRID, 256, SMEM_TOTAL_BYTES>>>(pairA, hn, 2, 5, b_self + 0 * D,
                                                             pairB, nullptr, N_NODES);

    agg_inter_kernel<<<AGG_GRID, 256>>>(pairB, hn);
    layer_kernel<2, 0><<<GEMM_GRID, 256, SMEM_TOTAL_BYTES>>>(pairB, hn, 3, 6, b_self + 1 * D,
                                                             pairA, nullptr, N_NODES);

    agg_inter_kernel<<<AGG_GRID, 256>>>(pairA, hn);
    layer_kernel<1, 1><<<GEMM_GRID, 256, SMEM_TOTAL_BYTES>>>(pairA, hn, 4, 7, b_self + 2 * D,
                                                             nullptr, out, N_NODES);
}

// round 16
// speedup vs baseline: 1.0496x; 1.0006x over previous
#include <cuda_runtime.h>
#include <cuda_fp16.h>
#include <cstdint>
#include <math.h>

#define N_NODES 50000
#define N_EDGES 800000
#define D 128

// ---------------- static scratch ----------------
__device__ float g_h [N_NODES * D];               // fp32 features ping
__device__ float g_h2[N_NODES * D];               // fp32 features pong
__device__ __align__(16) __half g_shA[N_NODES * D];  // fp16 shadow of ping
__device__ __align__(16) __half g_shB[N_NODES * D];  // fp16 shadow of pong
__device__ float g_hn[N_NODES * D];
__device__ int   g_deg[N_NODES];
__device__ float g_invdeg[N_NODES];
__device__ int   g_rowptr[N_NODES + 1];
__device__ int   g_pos[N_NODES];
__device__ int   g_col[N_EDGES];
__device__ __align__(16) __half g_Whi[8 * 16384];
__device__ __align__(16) __half g_Wlo[8 * 16384];

// ---------------- helpers ----------------
__device__ __forceinline__ uint32_t smem_u32(const void* p) {
    uint32_t a;
    asm("{ .reg .u64 t; cvta.to.shared.u64 t, %1; cvt.u32.u64 %0, t; }" : "=r"(a) : "l"(p));
    return a;
}
__device__ __forceinline__ void ldsm_x4(uint32_t* r, uint32_t addr) {
    asm volatile("ldmatrix.sync.aligned.m8n8.x4.shared.b16 {%0,%1,%2,%3}, [%4];"
                 : "=r"(r[0]), "=r"(r[1]), "=r"(r[2]), "=r"(r[3]) : "r"(addr));
}
__device__ __forceinline__ void ldsm_x2t(uint32_t* r, uint32_t addr) {
    asm volatile("ldmatrix.sync.aligned.m8n8.x2.trans.shared.b16 {%0,%1}, [%2];"
                 : "=r"(r[0]), "=r"(r[1]) : "r"(addr));
}
__device__ __forceinline__ void mma_f16(float* c, const uint32_t* a, const uint32_t* b) {
    asm volatile(
        "mma.sync.aligned.m16n8k16.row.col.f32.f16.f16.f32 "
        "{%0,%1,%2,%3}, {%4,%5,%6,%7}, {%8,%9}, {%0,%1,%2,%3};"
        : "+f"(c[0]), "+f"(c[1]), "+f"(c[2]), "+f"(c[3])
        : "r"(a[0]), "r"(a[1]), "r"(a[2]), "r"(a[3]), "r"(b[0]), "r"(b[1]));
}
__device__ __forceinline__ void split_pack4(float4 v, uint2& hi, uint2& lo) {
    __half h0 = __float2half_rn(v.x);
    __half h1 = __float2half_rn(v.y);
    __half h2 = __float2half_rn(v.z);
    __half h3 = __float2half_rn(v.w);
    __half l0 = __float2half_rn(v.x - __half2float(h0));
    __half l1 = __float2half_rn(v.y - __half2float(h1));
    __half l2 = __float2half_rn(v.z - __half2float(h2));
    __half l3 = __float2half_rn(v.w - __half2float(h3));
    hi.x = (uint32_t)__half_as_ushort(h0) | ((uint32_t)__half_as_ushort(h1) << 16);
    hi.y = (uint32_t)__half_as_ushort(h2) | ((uint32_t)__half_as_ushort(h3) << 16);
    lo.x = (uint32_t)__half_as_ushort(l0) | ((uint32_t)__half_as_ushort(l1) << 16);
    lo.y = (uint32_t)__half_as_ushort(l2) | ((uint32_t)__half_as_ushort(l3) << 16);
}

// ---------------- CSR build ----------------
__global__ void count_kernel(const int* __restrict__ dst) {
    int e = blockIdx.x * blockDim.x + threadIdx.x;
    if (e < N_EDGES) atomicAdd(&g_deg[dst[e]], 1);
}
__global__ void scan_kernel() {
    __shared__ int part[1024];
    const int CH = (N_NODES + 1023) / 1024;
    int t = threadIdx.x;
    int start = t * CH;
    int end = start + CH; if (end > N_NODES) end = N_NODES;
    int s = 0;
    for (int i = start; i < end; i++) s += g_deg[i];
    part[t] = s;
    __syncthreads();
    for (int off = 1; off < 1024; off <<= 1) {
        int v = 0;
        if (t >= off) v = part[t - off];
        __syncthreads();
        if (t >= off) part[t] += v;
        __syncthreads();
    }
    int run = (t == 0) ? 0 : part[t - 1];
    for (int i = start; i < end; i++) {
        g_rowptr[i] = run;
        g_pos[i]    = run;
        int d = g_deg[i];
        g_invdeg[i] = 1.0f / (float)(d > 1 ? d : 1);
        run += d;
    }
    if (t == 1023) g_rowptr[N_NODES] = part[1023];
}
__global__ void fill_kernel(const int* __restrict__ src, const int* __restrict__ dst) {
    int e = blockIdx.x * blockDim.x + threadIdx.x;
    if (e < N_EDGES) {
        int d = dst[e];
        int idx = atomicAdd(&g_pos[d], 1);
        g_col[idx] = src[e];
    }
}

// ---------------- prep: zero degrees + W fp32 -> hi/lo fp16 (8 slots) ----------------
__global__ void prep_kernel(const float* __restrict__ W1, const float* __restrict__ W2,
                            const float* __restrict__ Wself, const float* __restrict__ Wneigh) {
    int idx = blockIdx.x * blockDim.x + threadIdx.x;
    if (idx < N_NODES) g_deg[idx] = 0;
    if (idx >= 8 * 16384) return;
    int slot = idx >> 14, off = idx & 16383;
    const float* src;
    if (slot == 0)      src = W1;
    else if (slot == 1) src = W2;
    else if (slot < 5)  src = Wself + (size_t)(slot - 2) * 16384;
    else                src = Wneigh + (size_t)(slot - 5) * 16384;
    float v = src[off];
    __half h = __float2half_rn(v);
    g_Whi[idx] = h;
    g_Wlo[idx] = __float2half_rn(v - __half2float(h));
}

// ---------------- mean aggregation over fp16 shadow: 2 edges per warp-iter ----------------
__device__ __forceinline__ void accum8(float* acc, uint4 u) {
    float2 f;
    f = __half22float2(*(__half2*)&u.x); acc[0] += f.x; acc[1] += f.y;
    f = __half22float2(*(__half2*)&u.y); acc[2] += f.x; acc[3] += f.y;
    f = __half22float2(*(__half2*)&u.z); acc[4] += f.x; acc[5] += f.y;
    f = __half22float2(*(__half2*)&u.w); acc[6] += f.x; acc[7] += f.y;
}
__global__ void agg_h16_kernel(const __half* __restrict__ sh, float* __restrict__ hn) {
    int wid  = (blockIdx.x * blockDim.x + threadIdx.x) >> 5;
    int lane = threadIdx.x & 31;
    if (wid >= N_NODES) return;
    int beg = g_rowptr[wid], end = g_rowptr[wid + 1];
    int hf  = lane >> 4;       // half-warp: 0 or 1 (edge offset)
    int sub = lane & 15;       // covers 8 features each (16 lanes x 8 = 128)
    float acc[8] = {0.f, 0.f, 0.f, 0.f, 0.f, 0.f, 0.f, 0.f};
    int e = beg;
    for (; e + 4 <= end; e += 4) {
        uint4 u0 = *(const uint4*)(sh + (size_t)g_col[e + hf]     * D + sub * 8);
        uint4 u1 = *(const uint4*)(sh + (size_t)g_col[e + 2 + hf] * D + sub * 8);
        accum8(acc, u0);
        accum8(acc, u1);
    }
    if (e + 2 <= end) {
        uint4 u = *(const uint4*)(sh + (size_t)g_col[e + hf] * D + sub * 8);
        accum8(acc, u);
        e += 2;
    }
    if (e < end && hf == 0) {  // odd tail: half 0 takes it
        uint4 u = *(const uint4*)(sh + (size_t)g_col[e] * D + sub * 8);
        accum8(acc, u);
    }
    #pragma unroll
    for (int j = 0; j < 8; j++) acc[j] += __shfl_down_sync(0xffffffffu, acc[j], 16);
    if (hf == 0) {
        float inv = g_invdeg[wid];
        float* dst = hn + (size_t)wid * D + sub * 8;
        *(float4*)dst       = make_float4(acc[0] * inv, acc[1] * inv, acc[2] * inv, acc[3] * inv);
        *(float4*)(dst + 4) = make_float4(acc[4] * inv, acc[5] * inv, acc[6] * inv, acc[7] * inv);
    }
}

// ---------------- GEMM tile config (M tile = 64, 2 blocks/SM) ----------------
#define PITCH 272
#define MTILE 64
#define A_TILE_BYTES (MTILE * PITCH)   // 17408
#define B_TILE_BYTES (128 * PITCH)     // 34816
#define SMEM_TOTAL_BYTES (2 * A_TILE_BYTES + 2 * B_TILE_BYTES)  // 104448
#define STG_PITCH 132

__device__ __forceinline__ void load_split_A(const float* __restrict__ src, int row0, int n,
                                             char* As_hi, char* As_lo, int tid) {
    #pragma unroll 4
    for (int i = tid; i < 2048; i += 256) {
        int r = i >> 5, c = (i & 31) << 2;
        int gr = row0 + r;
        float4 v = make_float4(0.f, 0.f, 0.f, 0.f);
        if (gr < n) v = *(const float4*)(src + (size_t)gr * D + c);
        uint2 h, l;
        split_pack4(v, h, l);
        *(uint2*)(As_hi + r * PITCH + c * 2) = h;
        *(uint2*)(As_lo + r * PITCH + c * 2) = l;
    }
}

__device__ __forceinline__ void stage_split_A(const float* __restrict__ stg,
                                              char* As_hi, char* As_lo, int tid) {
    #pragma unroll 4
    for (int i = tid; i < 2048; i += 256) {
        int r = i >> 5, c = (i & 31) << 2;
        float4 v = *(const float4*)(stg + r * STG_PITCH + c);
        uint2 h, l;
        split_pack4(v, h, l);
        *(uint2*)(As_hi + r * PITCH + c * 2) = h;
        *(uint2*)(As_lo + r * PITCH + c * 2) = l;
    }
}

__device__ __forceinline__ void load_B_prepped(int slot, char* Bs_hi, char* Bs_lo, int tid) {
    const __half* whi = g_Whi + (size_t)slot * 16384;
    const __half* wlo = g_Wlo + (size_t)slot * 16384;
    #pragma unroll 4
    for (int i = tid; i < 2048; i += 256) {
        int r = i >> 4, c = (i & 15) << 3;
        *(uint4*)(Bs_hi + r * PITCH + c * 2) = *(const uint4*)(whi + r * D + c);
        *(uint4*)(Bs_lo + r * PITCH + c * 2) = *(const uint4*)(wlo + r * D + c);
    }
}

__device__ __forceinline__ void mma_mainloop(float acc[2][4][4], uint32_t a_hi0, uint32_t b_hi0) {
    #pragma unroll
    for (int k = 0; k < 8; k++) {
        uint32_t ah[2][4], al[2][4], bh[4][2], bl[4][2];
        #pragma unroll
        for (int nt = 0; nt < 4; nt++) {
            ldsm_x2t(bh[nt], b_hi0 + (uint32_t)k * (16 * PITCH) + nt * 16);
            ldsm_x2t(bl[nt], b_hi0 + B_TILE_BYTES + (uint32_t)k * (16 * PITCH) + nt * 16);
        }
        #pragma unroll
        for (int mt = 0; mt < 2; mt++) {
            ldsm_x4(ah[mt], a_hi0 + (uint32_t)mt * (16 * PITCH) + k * 32);
            ldsm_x4(al[mt], a_hi0 + A_TILE_BYTES + (uint32_t)mt * (16 * PITCH) + k * 32);
        }
        #pragma unroll
        for (int mt = 0; mt < 2; mt++)
            #pragma unroll
            for (int nt = 0; nt < 4; nt++) {
                mma_f16(acc[mt][nt], ah[mt], bh[nt]);
                mma_f16(acc[mt][nt], ah[mt], bl[nt]);
                mma_f16(acc[mt][nt], al[mt], bh[nt]);
            }
    }
}

__device__ __forceinline__ void zero_acc(float acc[2][4][4]) {
    #pragma unroll
    for (int mt = 0; mt < 2; mt++)
        #pragma unroll
        for (int nt = 0; nt < 4; nt++)
            #pragma unroll
            for (int q = 0; q < 4; q++) acc[mt][nt][q] = 0.f;
}

// OUTMODE 0: write fp32 buffer + fp16 shadow; OUTMODE 1: fp32 only (final out)
template <int ACT, int OUTMODE>
__device__ __forceinline__ void epilogue(float acc[2][4][4], const float* __restrict__ bias,
                                         float* __restrict__ out_f32,
                                         __half* __restrict__ out_sh,
                                         int row0, int n, int wm, int wn, int lane) {
    int mrow = lane >> 2;
    int mcol = (lane & 3) * 2;
    #pragma unroll
    for (int mt = 0; mt < 2; mt++)
        #pragma unroll
        for (int half = 0; half < 2; half++) {
            int gr = row0 + wm + mt * 16 + mrow + half * 8;
            if (gr < n) {
                size_t rb = (size_t)gr * D;
                #pragma unroll
                for (int nt = 0; nt < 4; nt++) {
                    int col = wn + nt * 8 + mcol;
                    float x0 = acc[mt][nt][half * 2 + 0];
                    float x1 = acc[mt][nt][half * 2 + 1];
                    if (bias) { x0 += bias[col]; x1 += bias[col + 1]; }
                    if (ACT == 1)      { x0 = tanhf(x0); x1 = tanhf(x1); }
                    else if (ACT == 2) { x0 = x0 / (1.f + expf(-x0)); x1 = x1 / (1.f + expf(-x1)); }
                    *(float2*)(out_f32 + rb + col) = make_float2(x0, x1);
                    if (OUTMODE == 0) {
                        __half2 hv = __floats2half2_rn(x0, x1);
                        *(uint32_t*)(out_sh + rb + col) = *(uint32_t*)&hv;
                    }
                }
            }
        }
}

// ---------------- fused fc_in: out = tanh(h@W1+b1)@W2 + b2 ----------------
__global__ void __launch_bounds__(256, 2)
fc_fused_kernel(const float* __restrict__ A, const float* __restrict__ b1,
                const float* __restrict__ b2,
                float* __restrict__ out_f32, __half* __restrict__ out_sh, int n) {
    extern __shared__ char smem[];
    char* As_hi = smem;
    char* As_lo = smem + A_TILE_BYTES;
    char* Bs_hi = smem + 2 * A_TILE_BYTES;
    float* staging = (float*)(smem + 2 * A_TILE_BYTES);

    int tid = threadIdx.x, lane = tid & 31, wid = tid >> 5;
    int row0 = blockIdx.x * MTILE;
    int wm = (wid & 1) * 32;
    int wn = (wid >> 1) * 32;
    int mrow = lane >> 2;
    int mcol = (lane & 3) * 2;

    uint32_t a_hi0 = smem_u32(As_hi) + (uint32_t)(wm + (lane & 15)) * PITCH + (lane >> 4) * 16;
    uint32_t b_hi0 = smem_u32(Bs_hi) + (uint32_t)(lane & 15) * PITCH + wn * 2;

    float acc[2][4][4];
    zero_acc(acc);

    load_split_A(A, row0, n, As_hi, As_lo, tid);
    load_B_prepped(0, Bs_hi, Bs_hi + B_TILE_BYTES, tid);
    __syncthreads();
    mma_mainloop(acc, a_hi0, b_hi0);
    __syncthreads();

    #pragma unroll
    for (int mt = 0; mt < 2; mt++)
        #pragma unroll
        for (int half = 0; half < 2; half++) {
            int r = wm + mt * 16 + mrow + half * 8;
            #pragma unroll
            for (int nt = 0; nt < 4; nt++) {
                int col = wn + nt * 8 + mcol;
                staging[r * STG_PITCH + col]     = tanhf(acc[mt][nt][half * 2 + 0] + b1[col]);
                staging[r * STG_PITCH + col + 1] = tanhf(acc[mt][nt][half * 2 + 1] + b1[col + 1]);
            }
        }
    __syncthreads();

    stage_split_A(staging, As_hi, As_lo, tid);
    __syncthreads();

    load_B_prepped(1, Bs_hi, Bs_hi + B_TILE_BYTES, tid);
    zero_acc(acc);
    __syncthreads();

    mma_mainloop(acc, a_hi0, b_hi0);
    epilogue<0, 0>(acc, b2, out_f32, out_sh, row0, n, wm, wn, lane);
}

// ---------------- fused SAGE layer: out = act(in@Ws + bias + hn@Wn) ----------------
template <int ACT, int OUTMODE>
__global__ void __launch_bounds__(256, 2)
layer_kernel(const float* __restrict__ in, const float* __restrict__ hn,
             int slot_self, int slot_neigh, const float* __restrict__ bias,
             float* __restrict__ out_f32, __half* __restrict__ out_sh, int n) {
    extern __shared__ char smem[];
    char* As_hi = smem;
    char* As_lo = smem + A_TILE_BYTES;
    char* Bs_hi = smem + 2 * A_TILE_BYTES;

    int tid = threadIdx.x, lane = tid & 31, wid = tid >> 5;
    int row0 = blockIdx.x * MTILE;
    int wm = (wid & 1) * 32;
    int wn = (wid >> 1) * 32;

    uint32_t a_hi0 = smem_u32(As_hi) + (uint32_t)(wm + (lane & 15)) * PITCH + (lane >> 4) * 16;
    uint32_t b_hi0 = smem_u32(Bs_hi) + (uint32_t)(lane & 15) * PITCH + wn * 2;

    float acc[2][4][4];
    zero_acc(acc);

    // phase 1: self term
    load_split_A(in, row0, n, As_hi, As_lo, tid);
    load_B_prepped(slot_self, Bs_hi, Bs_hi + B_TILE_BYTES, tid);
    __syncthreads();
    mma_mainloop(acc, a_hi0, b_hi0);
    __syncthreads();

    // phase 2: neighbor term
    load_split_A(hn, row0, n, As_hi, As_lo, tid);
    load_B_prepped(slot_neigh, Bs_hi, Bs_hi + B_TILE_BYTES, tid);
    __syncthreads();
    mma_mainloop(acc, a_hi0, b_hi0);

    epilogue<ACT, OUTMODE>(acc, bias, out_f32, out_sh, row0, n, wm, wn, lane);
}

// ---------------- launch ----------------
extern "C" void kernel_launch(void* const* d_in, const int* in_sizes, int n_in,
                              void* d_out, int out_size) {
    const float* h_in    = (const float*)d_in[0];
    const int*   src     = (const int*)  d_in[1];
    const int*   dst     = (const int*)  d_in[2];
    const float* W_in1   = (const float*)d_in[3];
    const float* b_in1   = (const float*)d_in[4];
    const float* W_in2   = (const float*)d_in[5];
    const float* b_in2   = (const float*)d_in[6];
    const float* W_self  = (const float*)d_in[7];
    const float* b_self  = (const float*)d_in[8];
    const float* W_neigh = (const float*)d_in[9];
    float* out = (float*)d_out;

    cudaFuncSetAttribute(fc_fused_kernel,    cudaFuncAttributeMaxDynamicSharedMemorySize, SMEM_TOTAL_BYTES);
    cudaFuncSetAttribute(layer_kernel<2, 0>, cudaFuncAttributeMaxDynamicSharedMemorySize, SMEM_TOTAL_BYTES);
    cudaFuncSetAttribute(layer_kernel<1, 1>, cudaFuncAttributeMaxDynamicSharedMemorySize, SMEM_TOTAL_BYTES);

    float *buf0 = nullptr, *buf1 = nullptr, *hn = nullptr;
    __half *shA = nullptr, *shB = nullptr;
    cudaGetSymbolAddress((void**)&buf0, g_h);
    cudaGetSymbolAddress((void**)&buf1, g_h2);
    cudaGetSymbolAddress((void**)&hn,   g_hn);
    cudaGetSymbolAddress((void**)&shA,  g_shA);
    cudaGetSymbolAddress((void**)&shB,  g_shB);

    const int GEMM_GRID = (N_NODES + MTILE - 1) / MTILE;  // 782
    const int EB = (N_EDGES + 255) / 256;
    const int AGG_GRID = (N_NODES * 32 + 255) / 256;

    // ---- prep + CSR build ----
    prep_kernel<<<512, 256>>>(W_in1, W_in2, W_self, W_neigh);
    count_kernel<<<EB, 256>>>(dst);
    scan_kernel<<<1, 1024>>>();
    fill_kernel<<<EB, 256>>>(src, dst);

    // ---- fc_in fused: buf0/shA = tanh(h@W1+b1)@W2 + b2 ----
    fc_fused_kernel<<<GEMM_GRID, 256, SMEM_TOTAL_BYTES>>>(h_in, b_in1, b_in2, buf0, shA, N_NODES);

    // ---- 3 SAGE layers: fp16-shadow gather (2 edges/iter) + fused dual-GEMM ----
    agg_h16_kernel<<<AGG_GRID, 256>>>(shA, hn);
    layer_kernel<2, 0><<<GEMM_GRID, 256, SMEM_TOTAL_BYTES>>>(buf0, hn, 2, 5, b_self + 0 * D,
                                                             buf1, shB, N_NODES);

    agg_h16_kernel<<<AGG_GRID, 256>>>(shB, hn);
    layer_kernel<2, 0><<<GEMM_GRID, 256, SMEM_TOTAL_BYTES>>>(buf1, hn, 3, 6, b_self + 1 * D,
                                                             buf0, shA, N_NODES);

    agg_h16_kernel<<<AGG_GRID, 256>>>(shA, hn);
    layer_kernel<1, 1><<<GEMM_GRID, 256, SMEM_TOTAL_BYTES>>>(buf0, hn, 4, 7, b_self + 2 * D,
                                                             out, nullptr, N_NODES);
}

// round 17
// speedup vs baseline: 1.1754x; 1.1198x over previous
#include <cuda_runtime.h>
#include <cuda_fp16.h>
#include <cstdint>
#include <math.h>

#define N_NODES 50000
#define N_EDGES 800000
#define D 128

// ---------------- static scratch ----------------
// features as fp16 hi/lo split arrays (exact fp32-to-2^-22 representation)
__device__ __align__(16) __half g_hiA[N_NODES * D];
__device__ __align__(16) __half g_loA[N_NODES * D];
__device__ __align__(16) __half g_hiB[N_NODES * D];
__device__ __align__(16) __half g_loB[N_NODES * D];
__device__ __align__(16) __half g_hn16[N_NODES * D];   // aggregated neighbors (fp16)
__device__ int   g_deg[N_NODES];
__device__ float g_invdeg[N_NODES];
__device__ int   g_rowptr[N_NODES + 1];
__device__ int   g_pos[N_NODES];
__device__ int   g_col[N_EDGES];
__device__ __align__(16) __half g_Whi[8 * 16384];
__device__ __align__(16) __half g_Wlo[8 * 16384];

// ---------------- helpers ----------------
__device__ __forceinline__ uint32_t smem_u32(const void* p) {
    uint32_t a;
    asm("{ .reg .u64 t; cvta.to.shared.u64 t, %1; cvt.u32.u64 %0, t; }" : "=r"(a) : "l"(p));
    return a;
}
__device__ __forceinline__ void ldsm_x4(uint32_t* r, uint32_t addr) {
    asm volatile("ldmatrix.sync.aligned.m8n8.x4.shared.b16 {%0,%1,%2,%3}, [%4];"
                 : "=r"(r[0]), "=r"(r[1]), "=r"(r[2]), "=r"(r[3]) : "r"(addr));
}
__device__ __forceinline__ void ldsm_x2t(uint32_t* r, uint32_t addr) {
    asm volatile("ldmatrix.sync.aligned.m8n8.x2.trans.shared.b16 {%0,%1}, [%2];"
                 : "=r"(r[0]), "=r"(r[1]) : "r"(addr));
}
__device__ __forceinline__ void mma_f16(float* c, const uint32_t* a, const uint32_t* b) {
    asm volatile(
        "mma.sync.aligned.m16n8k16.row.col.f32.f16.f16.f32 "
        "{%0,%1,%2,%3}, {%4,%5,%6,%7}, {%8,%9}, {%0,%1,%2,%3};"
        : "+f"(c[0]), "+f"(c[1]), "+f"(c[2]), "+f"(c[3])
        : "r"(a[0]), "r"(a[1]), "r"(a[2]), "r"(a[3]), "r"(b[0]), "r"(b[1]));
}
__device__ __forceinline__ void split_pack4(float4 v, uint2& hi, uint2& lo) {
    __half h0 = __float2half_rn(v.x);
    __half h1 = __float2half_rn(v.y);
    __half h2 = __float2half_rn(v.z);
    __half h3 = __float2half_rn(v.w);
    __half l0 = __float2half_rn(v.x - __half2float(h0));
    __half l1 = __float2half_rn(v.y - __half2float(h1));
    __half l2 = __float2half_rn(v.z - __half2float(h2));
    __half l3 = __float2half_rn(v.w - __half2float(h3));
    hi.x = (uint32_t)__half_as_ushort(h0) | ((uint32_t)__half_as_ushort(h1) << 16);
    hi.y = (uint32_t)__half_as_ushort(h2) | ((uint32_t)__half_as_ushort(h3) << 16);
    lo.x = (uint32_t)__half_as_ushort(l0) | ((uint32_t)__half_as_ushort(l1) << 16);
    lo.y = (uint32_t)__half_as_ushort(l2) | ((uint32_t)__half_as_ushort(l3) << 16);
}
__device__ __forceinline__ uint32_t split_pack2(float x0, float x1, uint32_t& lo) {
    __half h0 = __float2half_rn(x0);
    __half h1 = __float2half_rn(x1);
    __half l0 = __float2half_rn(x0 - __half2float(h0));
    __half l1 = __float2half_rn(x1 - __half2float(h1));
    lo = (uint32_t)__half_as_ushort(l0) | ((uint32_t)__half_as_ushort(l1) << 16);
    return (uint32_t)__half_as_ushort(h0) | ((uint32_t)__half_as_ushort(h1) << 16);
}

// ---------------- CSR build ----------------
__global__ void count_kernel(const int* __restrict__ dst) {
    int e = blockIdx.x * blockDim.x + threadIdx.x;
    if (e < N_EDGES) atomicAdd(&g_deg[dst[e]], 1);
}
__global__ void scan_kernel() {
    __shared__ int part[1024];
    const int CH = (N_NODES + 1023) / 1024;
    int t = threadIdx.x;
    int start = t * CH;
    int end = start + CH; if (end > N_NODES) end = N_NODES;
    int s = 0;
    for (int i = start; i < end; i++) s += g_deg[i];
    part[t] = s;
    __syncthreads();
    for (int off = 1; off < 1024; off <<= 1) {
        int v = 0;
        if (t >= off) v = part[t - off];
        __syncthreads();
        if (t >= off) part[t] += v;
        __syncthreads();
    }
    int run = (t == 0) ? 0 : part[t - 1];
    for (int i = start; i < end; i++) {
        g_rowptr[i] = run;
        g_pos[i]    = run;
        int d = g_deg[i];
        g_invdeg[i] = 1.0f / (float)(d > 1 ? d : 1);
        run += d;
    }
    if (t == 1023) g_rowptr[N_NODES] = part[1023];
}
__global__ void fill_kernel(const int* __restrict__ src, const int* __restrict__ dst) {
    int e = blockIdx.x * blockDim.x + threadIdx.x;
    if (e < N_EDGES) {
        int d = dst[e];
        int idx = atomicAdd(&g_pos[d], 1);
        g_col[idx] = src[e];
    }
}

// ---------------- prep: zero degrees + W fp32 -> hi/lo fp16 (8 slots) ----------------
__global__ void prep_kernel(const float* __restrict__ W1, const float* __restrict__ W2,
                            const float* __restrict__ Wself, const float* __restrict__ Wneigh) {
    int idx = blockIdx.x * blockDim.x + threadIdx.x;
    if (idx < N_NODES) g_deg[idx] = 0;
    if (idx >= 8 * 16384) return;
    int slot = idx >> 14, off = idx & 16383;
    const float* src;
    if (slot == 0)      src = W1;
    else if (slot == 1) src = W2;
    else if (slot < 5)  src = Wself + (size_t)(slot - 2) * 16384;
    else                src = Wneigh + (size_t)(slot - 5) * 16384;
    float v = src[off];
    __half h = __float2half_rn(v);
    g_Whi[idx] = h;
    g_Wlo[idx] = __float2half_rn(v - __half2float(h));
}

// ---------------- mean aggregation over fp16-hi (R13-proven shape), fp16 output ----------------
__global__ void agg_h16_kernel(const __half* __restrict__ hhi, __half* __restrict__ hn16) {
    int wid  = (blockIdx.x * blockDim.x + threadIdx.x) >> 5;
    int lane = threadIdx.x & 31;
    if (wid >= N_NODES) return;
    int beg = g_rowptr[wid], end = g_rowptr[wid + 1];
    float4 acc = make_float4(0.f, 0.f, 0.f, 0.f);
    int e = beg;
    for (; e + 4 <= end; e += 4) {
        uint2 u0 = *(const uint2*)(hhi + (size_t)g_col[e + 0] * D + lane * 4);
        uint2 u1 = *(const uint2*)(hhi + (size_t)g_col[e + 1] * D + lane * 4);
        uint2 u2 = *(const uint2*)(hhi + (size_t)g_col[e + 2] * D + lane * 4);
        uint2 u3 = *(const uint2*)(hhi + (size_t)g_col[e + 3] * D + lane * 4);
        float2 a0 = __half22float2(*(__half2*)&u0.x), b0 = __half22float2(*(__half2*)&u0.y);
        float2 a1 = __half22float2(*(__half2*)&u1.x), b1 = __half22float2(*(__half2*)&u1.y);
        float2 a2 = __half22float2(*(__half2*)&u2.x), b2 = __half22float2(*(__half2*)&u2.y);
        float2 a3 = __half22float2(*(__half2*)&u3.x), b3 = __half22float2(*(__half2*)&u3.y);
        acc.x += (a0.x + a1.x) + (a2.x + a3.x);
        acc.y += (a0.y + a1.y) + (a2.y + a3.y);
        acc.z += (b0.x + b1.x) + (b2.x + b3.x);
        acc.w += (b0.y + b1.y) + (b2.y + b3.y);
    }
    for (; e < end; e++) {
        uint2 u = *(const uint2*)(hhi + (size_t)g_col[e] * D + lane * 4);
        float2 a = __half22float2(*(__half2*)&u.x);
        float2 b = __half22float2(*(__half2*)&u.y);
        acc.x += a.x; acc.y += a.y; acc.z += b.x; acc.w += b.y;
    }
    float inv = g_invdeg[wid];
    __half2 h01 = __floats2half2_rn(acc.x * inv, acc.y * inv);
    __half2 h23 = __floats2half2_rn(acc.z * inv, acc.w * inv);
    uint2 w;
    w.x = *(uint32_t*)&h01;
    w.y = *(uint32_t*)&h23;
    *(uint2*)(hn16 + (size_t)wid * D + lane * 4) = w;
}

// ---------------- GEMM tile config (M tile = 64, 2 blocks/SM) ----------------
#define PITCH 272
#define MTILE 64
#define A_TILE_BYTES (MTILE * PITCH)   // 17408
#define B_TILE_BYTES (128 * PITCH)     // 34816
#define SMEM_TOTAL_BYTES (2 * A_TILE_BYTES + 2 * B_TILE_BYTES)  // 104448
#define STG_PITCH 132

__device__ __forceinline__ void load_split_A(const float* __restrict__ src, int row0, int n,
                                             char* As_hi, char* As_lo, int tid) {
    #pragma unroll 4
    for (int i = tid; i < 2048; i += 256) {
        int r = i >> 5, c = (i & 31) << 2;
        int gr = row0 + r;
        float4 v = make_float4(0.f, 0.f, 0.f, 0.f);
        if (gr < n) v = *(const float4*)(src + (size_t)gr * D + c);
        uint2 h, l;
        split_pack4(v, h, l);
        *(uint2*)(As_hi + r * PITCH + c * 2) = h;
        *(uint2*)(As_lo + r * PITCH + c * 2) = l;
    }
}

// pure copy from fp16 hi/lo arrays (R13-proven)
__device__ __forceinline__ void load_A_pair(const __half* __restrict__ hi,
                                            const __half* __restrict__ lo,
                                            int row0, int n,
                                            char* As_hi, char* As_lo, int tid) {
    #pragma unroll 4
    for (int i = tid; i < 2048; i += 256) {
        int arr = i >> 10;
        int j = i & 1023;
        int r = j >> 4, c = (j & 15) << 3;
        int gr = row0 + r;
        uint4 v = make_uint4(0u, 0u, 0u, 0u);
        const __half* src = arr ? lo : hi;
        if (gr < n) v = *(const uint4*)(src + (size_t)gr * D + c);
        char* dstbase = arr ? As_lo : As_hi;
        *(uint4*)(dstbase + r * PITCH + c * 2) = v;
    }
}

// pure copy of fp16 hn into As_hi only (phase-2 2-term path)
__device__ __forceinline__ void load_A_hi(const __half* __restrict__ hi, int row0, int n,
                                          char* As_hi, int tid) {
    #pragma unroll 4
    for (int i = tid; i < 1024; i += 256) {
        int r = i >> 4, c = (i & 15) << 3;
        int gr = row0 + r;
        uint4 v = make_uint4(0u, 0u, 0u, 0u);
        if (gr < n) v = *(const uint4*)(hi + (size_t)gr * D + c);
        *(uint4*)(As_hi + r * PITCH + c * 2) = v;
    }
}

__device__ __forceinline__ void stage_split_A(const float* __restrict__ stg,
                                              char* As_hi, char* As_lo, int tid) {
    #pragma unroll 4
    for (int i = tid; i < 2048; i += 256) {
        int r = i >> 5, c = (i & 31) << 2;
        float4 v = *(const float4*)(stg + r * STG_PITCH + c);
        uint2 h, l;
        split_pack4(v, h, l);
        *(uint2*)(As_hi + r * PITCH + c * 2) = h;
        *(uint2*)(As_lo + r * PITCH + c * 2) = l;
    }
}

__device__ __forceinline__ void load_B_prepped(int slot, char* Bs_hi, char* Bs_lo, int tid) {
    const __half* whi = g_Whi + (size_t)slot * 16384;
    const __half* wlo = g_Wlo + (size_t)slot * 16384;
    #pragma unroll 4
    for (int i = tid; i < 2048; i += 256) {
        int r = i >> 4, c = (i & 15) << 3;
        *(uint4*)(Bs_hi + r * PITCH + c * 2) = *(const uint4*)(whi + r * D + c);
        *(uint4*)(Bs_lo + r * PITCH + c * 2) = *(const uint4*)(wlo + r * D + c);
    }
}

// 3-term mainloop: acc += Ahi·Bhi + Ahi·Blo + Alo·Bhi
__device__ __forceinline__ void mma_mainloop3(float acc[2][4][4], uint32_t a_hi0, uint32_t b_hi0) {
    #pragma unroll
    for (int k = 0; k < 8; k++) {
        uint32_t ah[2][4], al[2][4], bh[4][2], bl[4][2];
        #pragma unroll
        for (int nt = 0; nt < 4; nt++) {
            ldsm_x2t(bh[nt], b_hi0 + (uint32_t)k * (16 * PITCH) + nt * 16);
            ldsm_x2t(bl[nt], b_hi0 + B_TILE_BYTES + (uint32_t)k * (16 * PITCH) + nt * 16);
        }
        #pragma unroll
        for (int mt = 0; mt < 2; mt++) {
            ldsm_x4(ah[mt], a_hi0 + (uint32_t)mt * (16 * PITCH) + k * 32);
            ldsm_x4(al[mt], a_hi0 + A_TILE_BYTES + (uint32_t)mt * (16 * PITCH) + k * 32);
        }
        #pragma unroll
        for (int mt = 0; mt < 2; mt++)
            #pragma unroll
            for (int nt = 0; nt < 4; nt++) {
                mma_f16(acc[mt][nt], ah[mt], bh[nt]);
                mma_f16(acc[mt][nt], ah[mt], bl[nt]);
                mma_f16(acc[mt][nt], al[mt], bh[nt]);
            }
    }
}

// 2-term mainloop (A exactly fp16): acc += Ahi·Bhi + Ahi·Blo
__device__ __forceinline__ void mma_mainloop2(float acc[2][4][4], uint32_t a_hi0, uint32_t b_hi0) {
    #pragma unroll
    for (int k = 0; k < 8; k++) {
        uint32_t ah[2][4], bh[4][2], bl[4][2];
        #pragma unroll
        for (int nt = 0; nt < 4; nt++) {
            ldsm_x2t(bh[nt], b_hi0 + (uint32_t)k * (16 * PITCH) + nt * 16);
            ldsm_x2t(bl[nt], b_hi0 + B_TILE_BYTES + (uint32_t)k * (16 * PITCH) + nt * 16);
        }
        #pragma unroll
        for (int mt = 0; mt < 2; mt++)
            ldsm_x4(ah[mt], a_hi0 + (uint32_t)mt * (16 * PITCH) + k * 32);
        #pragma unroll
        for (int mt = 0; mt < 2; mt++)
            #pragma unroll
            for (int nt = 0; nt < 4; nt++) {
                mma_f16(acc[mt][nt], ah[mt], bh[nt]);
                mma_f16(acc[mt][nt], ah[mt], bl[nt]);
            }
    }
}

__device__ __forceinline__ void zero_acc(float acc[2][4][4]) {
    #pragma unroll
    for (int mt = 0; mt < 2; mt++)
        #pragma unroll
        for (int nt = 0; nt < 4; nt++)
            #pragma unroll
            for (int q = 0; q < 4; q++) acc[mt][nt][q] = 0.f;
}

// OUTMODE 0: write fp16 hi/lo arrays; OUTMODE 1: fp32 (final out)
template <int ACT, int OUTMODE>
__device__ __forceinline__ void epilogue(float acc[2][4][4], const float* __restrict__ bias,
                                         __half* __restrict__ out_hi, __half* __restrict__ out_lo,
                                         float* __restrict__ out_f32,
                                         int row0, int n, int wm, int wn, int lane) {
    int mrow = lane >> 2;
    int mcol = (lane & 3) * 2;
    #pragma unroll
    for (int mt = 0; mt < 2; mt++)
        #pragma unroll
        for (int half = 0; half < 2; half++) {
            int gr = row0 + wm + mt * 16 + mrow + half * 8;
            if (gr < n) {
                size_t rb = (size_t)gr * D;
                #pragma unroll
                for (int nt = 0; nt < 4; nt++) {
                    int col = wn + nt * 8 + mcol;
                    float x0 = acc[mt][nt][half * 2 + 0];
                    float x1 = acc[mt][nt][half * 2 + 1];
                    if (bias) { x0 += bias[col]; x1 += bias[col + 1]; }
                    if (ACT == 1)      { x0 = tanhf(x0); x1 = tanhf(x1); }
                    else if (ACT == 2) { x0 = x0 / (1.f + expf(-x0)); x1 = x1 / (1.f + expf(-x1)); }
                    if (OUTMODE == 0) {
                        uint32_t lo, hi = split_pack2(x0, x1, lo);
                        *(uint32_t*)(out_hi + rb + col) = hi;
                        *(uint32_t*)(out_lo + rb + col) = lo;
                    } else {
                        *(float2*)(out_f32 + rb + col) = make_float2(x0, x1);
                    }
                }
            }
        }
}

// ---------------- fused fc_in: pair_out = tanh(h@W1+b1)@W2 + b2 ----------------
__global__ void __launch_bounds__(256, 2)
fc_fused_kernel(const float* __restrict__ A, const float* __restrict__ b1,
                const float* __restrict__ b2,
                __half* __restrict__ out_hi, __half* __restrict__ out_lo, int n) {
    extern __shared__ char smem[];
    char* As_hi = smem;
    char* As_lo = smem + A_TILE_BYTES;
    char* Bs_hi = smem + 2 * A_TILE_BYTES;
    float* staging = (float*)(smem + 2 * A_TILE_BYTES);

    int tid = threadIdx.x, lane = tid & 31, wid = tid >> 5;
    int row0 = blockIdx.x * MTILE;
    int wm = (wid & 1) * 32;
    int wn = (wid >> 1) * 32;
    int mrow = lane >> 2;
    int mcol = (lane & 3) * 2;

    uint32_t a_hi0 = smem_u32(As_hi) + (uint32_t)(wm + (lane & 15)) * PITCH + (lane >> 4) * 16;
    uint32_t b_hi0 = smem_u32(Bs_hi) + (uint32_t)(lane & 15) * PITCH + wn * 2;

    float acc[2][4][4];
    zero_acc(acc);

    load_split_A(A, row0, n, As_hi, As_lo, tid);
    load_B_prepped(0, Bs_hi, Bs_hi + B_TILE_BYTES, tid);
    __syncthreads();
    mma_mainloop3(acc, a_hi0, b_hi0);
    __syncthreads();

    #pragma unroll
    for (int mt = 0; mt < 2; mt++)
        #pragma unroll
        for (int half = 0; half < 2; half++) {
            int r = wm + mt * 16 + mrow + half * 8;
            #pragma unroll
            for (int nt = 0; nt < 4; nt++) {
                int col = wn + nt * 8 + mcol;
                staging[r * STG_PITCH + col]     = tanhf(acc[mt][nt][half * 2 + 0] + b1[col]);
                staging[r * STG_PITCH + col + 1] = tanhf(acc[mt][nt][half * 2 + 1] + b1[col + 1]);
            }
        }
    __syncthreads();

    stage_split_A(staging, As_hi, As_lo, tid);
    __syncthreads();

    load_B_prepped(1, Bs_hi, Bs_hi + B_TILE_BYTES, tid);
    zero_acc(acc);
    __syncthreads();

    mma_mainloop3(acc, a_hi0, b_hi0);
    epilogue<0, 0>(acc, b2, out_hi, out_lo, nullptr, row0, n, wm, wn, lane);
}

// ---------------- fused SAGE layer: out = act(in@Ws + bias + hn@Wn) ----------------
template <int ACT, int OUTMODE>
__global__ void __launch_bounds__(256, 2)
layer_kernel(const __half* __restrict__ in_hi, const __half* __restrict__ in_lo,
             const __half* __restrict__ hn16, int slot_self, int slot_neigh,
             const float* __restrict__ bias,
             __half* __restrict__ out_hi, __half* __restrict__ out_lo,
             float* __restrict__ out_f32, int n) {
    extern __shared__ char smem[];
    char* As_hi = smem;
    char* As_lo = smem + A_TILE_BYTES;
    char* Bs_hi = smem + 2 * A_TILE_BYTES;

    int tid = threadIdx.x, lane = tid & 31, wid = tid >> 5;
    int row0 = blockIdx.x * MTILE;
    int wm = (wid & 1) * 32;
    int wn = (wid >> 1) * 32;

    uint32_t a_hi0 = smem_u32(As_hi) + (uint32_t)(wm + (lane & 15)) * PITCH + (lane >> 4) * 16;
    uint32_t b_hi0 = smem_u32(Bs_hi) + (uint32_t)(lane & 15) * PITCH + wn * 2;

    float acc[2][4][4];
    zero_acc(acc);

    // phase 1: self term (3-term, A from fp16 pair — pure copy)
    load_A_pair(in_hi, in_lo, row0, n, As_hi, As_lo, tid);
    load_B_prepped(slot_self, Bs_hi, Bs_hi + B_TILE_BYTES, tid);
    __syncthreads();
    mma_mainloop3(acc, a_hi0, b_hi0);
    __syncthreads();

    // phase 2: neighbor term (A exactly fp16 -> 2-term; As_lo unused)
    load_A_hi(hn16, row0, n, As_hi, tid);
    load_B_prepped(slot_neigh, Bs_hi, Bs_hi + B_TILE_BYTES, tid);
    __syncthreads();
    mma_mainloop2(acc, a_hi0, b_hi0);

    epilogue<ACT, OUTMODE>(acc, bias, out_hi, out_lo, out_f32, row0, n, wm, wn, lane);
}

// ---------------- launch ----------------
extern "C" void kernel_launch(void* const* d_in, const int* in_sizes, int n_in,
                              void* d_out, int out_size) {
    const float* h_in    = (const float*)d_in[0];
    const int*   src     = (const int*)  d_in[1];
    const int*   dst     = (const int*)  d_in[2];
    const float* W_in1   = (const float*)d_in[3];
    const float* b_in1   = (const float*)d_in[4];
    const float* W_in2   = (const float*)d_in[5];
    const float* b_in2   = (const float*)d_in[6];
    const float* W_self  = (const float*)d_in[7];
    const float* b_self  = (const float*)d_in[8];
    const float* W_neigh = (const float*)d_in[9];
    float* out = (float*)d_out;

    cudaFuncSetAttribute(fc_fused_kernel,    cudaFuncAttributeMaxDynamicSharedMemorySize, SMEM_TOTAL_BYTES);
    cudaFuncSetAttribute(layer_kernel<2, 0>, cudaFuncAttributeMaxDynamicSharedMemorySize, SMEM_TOTAL_BYTES);
    cudaFuncSetAttribute(layer_kernel<1, 1>, cudaFuncAttributeMaxDynamicSharedMemorySize, SMEM_TOTAL_BYTES);

    __half *hiA = nullptr, *loA = nullptr, *hiB = nullptr, *loB = nullptr, *hn16 = nullptr;
    cudaGetSymbolAddress((void**)&hiA,  g_hiA);
    cudaGetSymbolAddress((void**)&loA,  g_loA);
    cudaGetSymbolAddress((void**)&hiB,  g_hiB);
    cudaGetSymbolAddress((void**)&loB,  g_loB);
    cudaGetSymbolAddress((void**)&hn16, g_hn16);

    const int GEMM_GRID = (N_NODES + MTILE - 1) / MTILE;  // 782
    const int EB = (N_EDGES + 255) / 256;
    const int AGG_GRID = (N_NODES * 32 + 255) / 256;

    // ---- prep + CSR build ----
    prep_kernel<<<512, 256>>>(W_in1, W_in2, W_self, W_neigh);
    count_kernel<<<EB, 256>>>(dst);
    scan_kernel<<<1, 1024>>>();
    fill_kernel<<<EB, 256>>>(src, dst);

    // ---- fc_in fused: pairA = tanh(h@W1+b1)@W2 + b2 ----
    fc_fused_kernel<<<GEMM_GRID, 256, SMEM_TOTAL_BYTES>>>(h_in, b_in1, b_in2, hiA, loA, N_NODES);

    // ---- 3 SAGE layers ----
    agg_h16_kernel<<<AGG_GRID, 256>>>(hiA, hn16);
    layer_kernel<2, 0><<<GEMM_GRID, 256, SMEM_TOTAL_BYTES>>>(hiA, loA, hn16, 2, 5, b_self + 0 * D,
                                                             hiB, loB, nullptr, N_NODES);

    agg_h16_kernel<<<AGG_GRID, 256>>>(hiB, hn16);
    layer_kernel<2, 0><<<GEMM_GRID, 256, SMEM_TOTAL_BYTES>>>(hiB, loB, hn16, 3, 6, b_self + 1 * D,
                                                             hiA, loA, nullptr, N_NODES);

    agg_h16_kernel<<<AGG_GRID, 256>>>(hiA, hn16);
    layer_kernel<1, 1><<<GEMM_GRID, 256, SMEM_TOTAL_BYTES>>>(hiA, loA, hn16, 4, 7, b_self + 2 * D,
                                                             nullptr, nullptr, out, N_NODES);
}